// round 4
// baseline (speedup 1.0000x reference)
#include <cuda_runtime.h>
#include <cuda_bf16.h>
#include <math.h>

// ---------------------------------------------------------------------------
// Problem constants
// ---------------------------------------------------------------------------
#define D_MODEL   256
#define N_HEADS   8
#define HEAD_DIM  32
#define N_LEVELS  4
#define N_POINTS  4
#define D_FFN     1024
#define HW        128
#define LQ        (HW * HW)            // 16384
#define LIN       (N_LEVELS * LQ)      // 65536
#define BATCH     2

#define M_Q       (BATCH * LQ)         // 32768
#define M_V       (BATCH * LIN)        // 131072

// ---------------------------------------------------------------------------
// Scratch (device globals -- no dynamic allocation allowed)
// ---------------------------------------------------------------------------
__device__ float g_q      [M_Q * D_MODEL];       // q = cur_src + pos[:, -1]
__device__ float g_value  [M_V * D_MODEL];       // value projection
__device__ float g_off    [M_Q * D_MODEL];       // sampling offsets (256 ch)
__device__ float g_attn   [M_Q * 128];           // attn logits -> softmaxed
__device__ float g_attnout[M_Q * D_MODEL];       // deformable attn output
__device__ float g_src2   [M_Q * D_MODEL];       // proj / ffn2 output (reused)
__device__ float g_src    [M_Q * D_MODEL];       // after first LN
__device__ float g_ffn    [M_Q * D_FFN];         // ffn hidden

// ---------------------------------------------------------------------------
// Generic tiled fp32 GEMM:  C[M,N] = (A (+ A2)) @ B[K,N] + bias, optional ReLU
// BM=BN=128, BK=16, 256 threads, 8x8 per-thread tile.
// M % 128 == 0, N % 128 == 0, K % 16 == 0 (true for all calls here).
// ---------------------------------------------------------------------------
template <bool RELU>
__global__ void __launch_bounds__(256)
gemm_kernel(const float* __restrict__ A, const float* __restrict__ A2,
            const float* __restrict__ B, const float* __restrict__ bias,
            float* __restrict__ C, int M, int N, int K)
{
    __shared__ float As[16][132];   // padded to kill store bank conflicts
    __shared__ float Bs[16][128];

    const int bx = blockIdx.x;      // N tile
    const int by = blockIdx.y;      // M tile
    const int tid = threadIdx.x;
    const int tm = tid >> 4;        // 0..15
    const int tn = tid & 15;        // 0..15

    const float* Ab  = A  + (size_t)by * 128 * K;
    const float* A2b = A2 ? (A2 + (size_t)by * 128 * K) : nullptr;
    const float* Bb  = B + (size_t)bx * 128;

    float acc[8][8];
#pragma unroll
    for (int i = 0; i < 8; i++)
#pragma unroll
        for (int j = 0; j < 8; j++) acc[i][j] = 0.f;

    for (int k0 = 0; k0 < K; k0 += 16) {
        // Load A tile (128x16) as 512 float4s, store transposed
#pragma unroll
        for (int it = 0; it < 2; it++) {
            int idx = tid + it * 256;
            int row = idx >> 2;
            int kq  = idx & 3;
            float4 v = *(const float4*)(Ab + (size_t)row * K + k0 + kq * 4);
            if (A2b) {
                float4 w = *(const float4*)(A2b + (size_t)row * K + k0 + kq * 4);
                v.x += w.x; v.y += w.y; v.z += w.z; v.w += w.w;
            }
            As[kq * 4 + 0][row] = v.x;
            As[kq * 4 + 1][row] = v.y;
            As[kq * 4 + 2][row] = v.z;
            As[kq * 4 + 3][row] = v.w;
        }
        // Load B tile (16x128)
#pragma unroll
        for (int it = 0; it < 2; it++) {
            int idx = tid + it * 256;
            int krow = idx >> 5;
            int nq   = idx & 31;
            *(float4*)(&Bs[krow][nq * 4]) =
                *(const float4*)(Bb + (size_t)(k0 + krow) * N + nq * 4);
        }
        __syncthreads();

#pragma unroll
        for (int k = 0; k < 16; k++) {
            float a[8], b[8];
#pragma unroll
            for (int i = 0; i < 8; i++) a[i] = As[k][tm * 8 + i];
#pragma unroll
            for (int j = 0; j < 8; j++) b[j] = Bs[k][tn * 8 + j];
#pragma unroll
            for (int i = 0; i < 8; i++)
#pragma unroll
                for (int j = 0; j < 8; j++)
                    acc[i][j] = fmaf(a[i], b[j], acc[i][j]);
        }
        __syncthreads();
    }

    // Epilogue: bias (+ReLU), vectorized stores
    float bv[8];
    const float* bp = bias + (size_t)bx * 128 + tn * 8;
#pragma unroll
    for (int j = 0; j < 8; j++) bv[j] = bp[j];

#pragma unroll
    for (int i = 0; i < 8; i++) {
        float* Crow = C + (size_t)(by * 128 + tm * 8 + i) * N + bx * 128 + tn * 8;
#pragma unroll
        for (int j0 = 0; j0 < 8; j0 += 4) {
            float4 o;
            o.x = acc[i][j0 + 0] + bv[j0 + 0];
            o.y = acc[i][j0 + 1] + bv[j0 + 1];
            o.z = acc[i][j0 + 2] + bv[j0 + 2];
            o.w = acc[i][j0 + 3] + bv[j0 + 3];
            if (RELU) {
                o.x = fmaxf(o.x, 0.f); o.y = fmaxf(o.y, 0.f);
                o.z = fmaxf(o.z, 0.f); o.w = fmaxf(o.w, 0.f);
            }
            *(float4*)(Crow + j0) = o;
        }
    }
}

// ---------------------------------------------------------------------------
// q = cur_src + pos[:, 3]   (level-3 slice of pos)
// ---------------------------------------------------------------------------
__global__ void q_kernel(const float* __restrict__ cur,
                         const float* __restrict__ pos,
                         float* __restrict__ q)
{
    size_t t = (size_t)blockIdx.x * blockDim.x + threadIdx.x;   // float4 index
    const size_t per_batch = (size_t)LQ * D_MODEL / 4;          // 1048576
    size_t n = t / per_batch;
    size_t r = t - n * per_batch;
    float4 a = ((const float4*)cur)[t];
    float4 b = ((const float4*)pos)[(n * N_LEVELS + (N_LEVELS - 1)) * per_batch + r];
    a.x += b.x; a.y += b.y; a.z += b.z; a.w += b.w;
    ((float4*)q)[t] = a;
}

// ---------------------------------------------------------------------------
// In-place softmax over groups of 16 (per n,q,head)
// ---------------------------------------------------------------------------
__global__ void softmax16_kernel(float* __restrict__ attn)
{
    int t = blockIdx.x * blockDim.x + threadIdx.x;   // 0 .. M_Q*8-1
    float* p = attn + (size_t)(t >> 3) * 128 + (t & 7) * 16;
    float4 v[4];
#pragma unroll
    for (int i = 0; i < 4; i++) v[i] = ((float4*)p)[i];
    float* f = (float*)v;
    float mx = f[0];
#pragma unroll
    for (int i = 1; i < 16; i++) mx = fmaxf(mx, f[i]);
    float s = 0.f;
#pragma unroll
    for (int i = 0; i < 16; i++) { f[i] = expf(f[i] - mx); s += f[i]; }
    float inv = 1.f / s;
#pragma unroll
    for (int i = 0; i < 16; i++) f[i] *= inv;
#pragma unroll
    for (int i = 0; i < 4; i++) ((float4*)p)[i] = v[i];
}

// ---------------------------------------------------------------------------
// Deformable attention sampling. One warp per (n, q, head); lane = channel.
// value layout: (n, level*16384 + y*128 + x, head, ch)
// off  layout:  (n, q, head, level, point, 2)  -> 256 ch
// attn layout:  (n, q, head, level*4+point)    -> 128 ch (post-softmax)
// out  layout:  (n, q, head*32 + ch)
// ---------------------------------------------------------------------------
__global__ void __launch_bounds__(256)
sample_kernel(const float* __restrict__ ref, float* __restrict__ out)
{
    int wg   = (blockIdx.x * blockDim.x + threadIdx.x) >> 5;  // 0 .. M_Q*8-1
    int lane = threadIdx.x & 31;
    int h = wg & 7;
    int q = (wg >> 3) & (LQ - 1);
    int n = wg >> 17;

    const size_t nq = (size_t)n * LQ + q;
    const float* offp  = g_off  + nq * 256 + h * 32;   // [l*8 + p*2 + xy]
    const float* attnp = g_attn + nq * 128 + h * 16;   // [l*4 + p]
    const float* refp  = ref    + nq * (N_LEVELS * 2); // [l*2 + xy]

    float acc = 0.f;

#pragma unroll
    for (int l = 0; l < N_LEVELS; l++) {
        float rx = refp[l * 2 + 0] * (float)HW - 0.5f;
        float ry = refp[l * 2 + 1] * (float)HW - 0.5f;
        const float* vbase = g_value
            + ((size_t)(n * LIN + l * LQ)) * D_MODEL + h * 32 + lane;

#pragma unroll
        for (int p = 0; p < N_POINTS; p++) {
            float x  = rx + offp[l * 8 + p * 2 + 0];
            float y  = ry + offp[l * 8 + p * 2 + 1];
            float aw = attnp[l * 4 + p];

            float x0f = floorf(x), y0f = floorf(y);
            float wx = x - x0f, wy = y - y0f;
            int x0 = (int)x0f, y0 = (int)y0f;
            int x1 = x0 + 1,   y1 = y0 + 1;

            float mx0 = (x0 >= 0 && x0 < HW) ? 1.f : 0.f;
            float mx1 = (x1 >= 0 && x1 < HW) ? 1.f : 0.f;
            float my0 = (y0 >= 0 && y0 < HW) ? 1.f : 0.f;
            float my1 = (y1 >= 0 && y1 < HW) ? 1.f : 0.f;

            int cx0 = min(max(x0, 0), HW - 1);
            int cx1 = min(max(x1, 0), HW - 1);
            int cy0 = min(max(y0, 0), HW - 1);
            int cy1 = min(max(y1, 0), HW - 1);

            float w00 = (1.f - wx) * (1.f - wy) * mx0 * my0;
            float w10 = wx * (1.f - wy) * mx1 * my0;
            float w01 = (1.f - wx) * wy * mx0 * my1;
            float w11 = wx * wy * mx1 * my1;

            float v00 = vbase[(size_t)(cy0 * HW + cx0) * D_MODEL];
            float v10 = vbase[(size_t)(cy0 * HW + cx1) * D_MODEL];
            float v01 = vbase[(size_t)(cy1 * HW + cx0) * D_MODEL];
            float v11 = vbase[(size_t)(cy1 * HW + cx1) * D_MODEL];

            float s = w00 * v00 + w10 * v10 + w01 * v01 + w11 * v11;
            acc = fmaf(aw, s, acc);
        }
    }

    out[nq * D_MODEL + h * 32 + lane] = acc;
}

// ---------------------------------------------------------------------------
// Fused residual-add + LayerNorm over 256-wide rows. One warp per row.
// ---------------------------------------------------------------------------
__global__ void __launch_bounds__(256)
add_ln_kernel(const float* __restrict__ a, const float* __restrict__ b,
              const float* __restrict__ gamma, const float* __restrict__ beta,
              float* __restrict__ out)
{
    int row  = (blockIdx.x * blockDim.x + threadIdx.x) >> 5;
    int lane = threadIdx.x & 31;

    const float4* a4 = (const float4*)(a + (size_t)row * D_MODEL);
    const float4* b4 = (const float4*)(b + (size_t)row * D_MODEL);

    float x[8];
    float4 va0 = a4[lane * 2 + 0], vb0 = b4[lane * 2 + 0];
    float4 va1 = a4[lane * 2 + 1], vb1 = b4[lane * 2 + 1];
    x[0] = va0.x + vb0.x; x[1] = va0.y + vb0.y;
    x[2] = va0.z + vb0.z; x[3] = va0.w + vb0.w;
    x[4] = va1.x + vb1.x; x[5] = va1.y + vb1.y;
    x[6] = va1.z + vb1.z; x[7] = va1.w + vb1.w;

    float s = 0.f, ss = 0.f;
#pragma unroll
    for (int i = 0; i < 8; i++) { s += x[i]; ss = fmaf(x[i], x[i], ss); }
#pragma unroll
    for (int d = 16; d > 0; d >>= 1) {
        s  += __shfl_xor_sync(0xffffffffu, s,  d);
        ss += __shfl_xor_sync(0xffffffffu, ss, d);
    }
    float mean = s * (1.f / D_MODEL);
    float var  = ss * (1.f / D_MODEL) - mean * mean;
    float inv  = rsqrtf(var + 1e-5f);

    float o[8];
#pragma unroll
    for (int i = 0; i < 8; i++) {
        int c = lane * 8 + i;
        o[i] = (x[i] - mean) * inv * gamma[c] + beta[c];
    }
    float4* o4 = (float4*)(out + (size_t)row * D_MODEL);
    o4[lane * 2 + 0] = make_float4(o[0], o[1], o[2], o[3]);
    o4[lane * 2 + 1] = make_float4(o[4], o[5], o[6], o[7]);
}

// ---------------------------------------------------------------------------
// Launch
// ---------------------------------------------------------------------------
extern "C" void kernel_launch(void* const* d_in, const int* in_sizes, int n_in,
                              void* d_out, int out_size)
{
    const float* cur_src = (const float*)d_in[0];
    const float* src_all = (const float*)d_in[1];
    const float* pos     = (const float*)d_in[2];
    const float* refpts  = (const float*)d_in[3];
    // d_in[4] spatial_shape (static), d_in[5] level_start_index (static)
    const float* W_off  = (const float*)d_in[6];
    const float* b_off  = (const float*)d_in[7];
    const float* W_attn = (const float*)d_in[8];
    const float* b_attn = (const float*)d_in[9];
    const float* W_val  = (const float*)d_in[10];
    const float* b_val  = (const float*)d_in[11];
    const float* W_out  = (const float*)d_in[12];
    const float* b_out  = (const float*)d_in[13];
    const float* gamma1 = (const float*)d_in[14];
    const float* beta1  = (const float*)d_in[15];
    const float* W1     = (const float*)d_in[16];
    const float* b1     = (const float*)d_in[17];
    const float* W2     = (const float*)d_in[18];
    const float* b2     = (const float*)d_in[19];
    const float* gamma2 = (const float*)d_in[20];
    const float* beta2  = (const float*)d_in[21];
    float* out = (float*)d_out;

    float *q_buf, *value_buf, *off_buf, *attn_buf, *attnout_buf,
          *src2_buf, *src_buf, *ffn_buf;
    cudaGetSymbolAddress((void**)&q_buf,       g_q);
    cudaGetSymbolAddress((void**)&value_buf,   g_value);
    cudaGetSymbolAddress((void**)&off_buf,     g_off);
    cudaGetSymbolAddress((void**)&attn_buf,    g_attn);
    cudaGetSymbolAddress((void**)&attnout_buf, g_attnout);
    cudaGetSymbolAddress((void**)&src2_buf,    g_src2);
    cudaGetSymbolAddress((void**)&src_buf,     g_src);
    cudaGetSymbolAddress((void**)&ffn_buf,     g_ffn);

    // 1) q = cur_src + pos[:,-1]
    {
        int nvec = M_Q * D_MODEL / 4;   // 2097152 float4s
        q_kernel<<<nvec / 256, 256>>>(cur_src, pos, q_buf);
    }

    // 2) value = (src_all + pos_flat) @ W_val + b_val
    gemm_kernel<false><<<dim3(D_MODEL / 128, M_V / 128), 256>>>(
        src_all, pos, W_val, b_val, value_buf, M_V, D_MODEL, D_MODEL);

    // 3) off = q @ W_off + b_off
    gemm_kernel<false><<<dim3(D_MODEL / 128, M_Q / 128), 256>>>(
        q_buf, nullptr, W_off, b_off, off_buf, M_Q, D_MODEL, D_MODEL);

    // 4) attn logits = q @ W_attn + b_attn
    gemm_kernel<false><<<dim3(128 / 128, M_Q / 128), 256>>>(
        q_buf, nullptr, W_attn, b_attn, attn_buf, M_Q, 128, D_MODEL);

    // 5) softmax over 16-groups
    softmax16_kernel<<<(M_Q * N_HEADS) / 256, 256>>>(attn_buf);

    // 6) deformable sampling
    sample_kernel<<<(M_Q * N_HEADS * 32) / 256, 256>>>(refpts, attnout_buf);

    // 7) src2 = attnout @ W_out + b_out
    gemm_kernel<false><<<dim3(D_MODEL / 128, M_Q / 128), 256>>>(
        attnout_buf, nullptr, W_out, b_out, src2_buf, M_Q, D_MODEL, D_MODEL);

    // 8) src = LN(cur_src + src2)
    add_ln_kernel<<<(M_Q * 32) / 256, 256>>>(
        cur_src, src2_buf, gamma1, beta1, src_buf);

    // 9) ffn hidden = relu(src @ W1 + b1)
    gemm_kernel<true><<<dim3(D_FFN / 128, M_Q / 128), 256>>>(
        src_buf, nullptr, W1, b1, ffn_buf, M_Q, D_FFN, D_MODEL);

    // 10) ffn out = hidden @ W2 + b2  (reuse src2 buffer)
    gemm_kernel<false><<<dim3(D_MODEL / 128, M_Q / 128), 256>>>(
        ffn_buf, nullptr, W2, b2, src2_buf, M_Q, D_MODEL, D_FFN);

    // 11) out = LN(src + ffn_out)
    add_ln_kernel<<<(M_Q * 32) / 256, 256>>>(
        src_buf, src2_buf, gamma2, beta2, out);
}

// round 7
// speedup vs baseline: 1.9212x; 1.9212x over previous
#include <cuda_runtime.h>
#include <cuda_bf16.h>
#include <math.h>
#include <stdint.h>

// ---------------------------------------------------------------------------
// Problem constants
// ---------------------------------------------------------------------------
#define D_MODEL   256
#define N_HEADS   8
#define HEAD_DIM  32
#define N_LEVELS  4
#define N_POINTS  4
#define D_FFN     1024
#define HW        128
#define LQ        (HW * HW)            // 16384
#define LIN       (N_LEVELS * LQ)      // 65536
#define BATCH     2

#define M_Q       (BATCH * LQ)         // 32768
#define M_V       (BATCH * LIN)        // 131072

// ---------------------------------------------------------------------------
// Scratch (device globals -- no dynamic allocation allowed)
// ---------------------------------------------------------------------------
__device__ float g_q      [M_Q * D_MODEL];
__device__ float g_value  [M_V * D_MODEL];
__device__ float g_off    [M_Q * D_MODEL];
__device__ float g_attn   [M_Q * 128];
__device__ float g_attnout[M_Q * D_MODEL];
__device__ float g_src2   [M_Q * D_MODEL];
__device__ float g_src    [M_Q * D_MODEL];
__device__ float g_ffn    [M_Q * D_FFN];

// ---------------------------------------------------------------------------
// TF32 tensor-core GEMM:  C[M,N] = (A (+A2)) @ B[K,N] + bias, optional ReLU
// BM=BN=128, BK=16, 256 threads (8 warps, 2x4), warp tile 64x32,
// mma.sync.aligned.m16n8k8.row.col.f32.tf32.tf32.f32,
// cp.async double-buffered smem, conflict-free padded layouts.
// Requires M%128==0, N%128==0, K%16==0 (true for all calls).
// ---------------------------------------------------------------------------
#define BM 128
#define BN 128
#define BK 16
#define ARS (BK + 4)     // A row stride (floats): [m][k], 20
#define BRS (BN + 8)     // B row stride (floats): [k][n], 136

__device__ __forceinline__ uint32_t f2tf(float x) {
    uint32_t r;
    asm("cvt.rna.tf32.f32 %0, %1;" : "=r"(r) : "f"(x));
    return r;
}

__device__ __forceinline__ void cpasync16(void* smem_dst, const void* gsrc) {
    uint32_t s = (uint32_t)__cvta_generic_to_shared(smem_dst);
    asm volatile("cp.async.cg.shared.global [%0], [%1], 16;\n"
                 :: "r"(s), "l"(gsrc));
}

template <bool RELU, bool FUSE_ADD>
__global__ void __launch_bounds__(256)
mma_gemm(const float* __restrict__ A, const float* __restrict__ A2,
         const float* __restrict__ B, const float* __restrict__ bias,
         float* __restrict__ C, int M, int N, int K)
{
    __shared__ float As[2][BM][ARS];
    __shared__ float Bs[2][BK][BRS];

    const int tid  = threadIdx.x;
    const int lane = tid & 31;
    const int warp = tid >> 5;
    const int gid  = lane >> 2;       // 0..7
    const int tig  = lane & 3;        // 0..3
    const int wm   = warp >> 2;       // 0..1 -> 64 rows
    const int wn   = warp & 3;        // 0..3 -> 32 cols

    const int bx = blockIdx.x;
    const int by = blockIdx.y;

    const float* Ab  = A + (size_t)by * BM * K;
    const float* A2b = FUSE_ADD ? (A2 + (size_t)by * BM * K) : nullptr;
    const float* Bb  = B + (size_t)bx * BN;

    // load-assignment (constant per thread)
    const int ar0 = tid >> 2;                // A rows for the 2 f4 loads
    const int ac0 = (tid & 3) * 4;
    const int br0 = tid >> 5;                // B rows
    const int bc0 = (tid & 31) * 4;

    float acc[4][4][4];
#pragma unroll
    for (int i = 0; i < 4; i++)
#pragma unroll
        for (int j = 0; j < 4; j++)
#pragma unroll
            for (int r = 0; r < 4; r++) acc[i][j][r] = 0.f;

    const int T = K / BK;

    // ---- tile loader ----
    auto load_tile = [&](int t, int buf) {
#pragma unroll
        for (int i = 0; i < 2; i++) {
            int row = ar0 + i * 64;
            const float* src = Ab + (size_t)row * K + t * BK + ac0;
            if (FUSE_ADD) {
                float4 v = *(const float4*)src;
                float4 w = *(const float4*)(A2b + (size_t)row * K + t * BK + ac0);
                v.x += w.x; v.y += w.y; v.z += w.z; v.w += w.w;
                *(float4*)(&As[buf][row][ac0]) = v;
            } else {
                cpasync16(&As[buf][row][ac0], src);
            }
        }
#pragma unroll
        for (int i = 0; i < 2; i++) {
            int row = br0 + i * 8;
            cpasync16(&Bs[buf][row][bc0],
                      Bb + (size_t)(t * BK + row) * N + bc0);
        }
    };

    load_tile(0, 0);
    asm volatile("cp.async.commit_group;\n");

    for (int t = 0; t < T; t++) {
        asm volatile("cp.async.wait_group 0;\n");
        __syncthreads();
        int cur = t & 1;
        if (t + 1 < T) load_tile(t + 1, cur ^ 1);
        asm volatile("cp.async.commit_group;\n");

        const int mrow = wm * 64;
        const int ncol = wn * 32;
#pragma unroll
        for (int kk = 0; kk < BK; kk += 8) {
            uint32_t a[4][4];
#pragma unroll
            for (int mf = 0; mf < 4; mf++) {
                int m = mrow + mf * 16;
                a[mf][0] = f2tf(As[cur][m + gid    ][kk + tig    ]);
                a[mf][1] = f2tf(As[cur][m + gid + 8][kk + tig    ]);
                a[mf][2] = f2tf(As[cur][m + gid    ][kk + tig + 4]);
                a[mf][3] = f2tf(As[cur][m + gid + 8][kk + tig + 4]);
            }
            uint32_t bf[4][2];
#pragma unroll
            for (int nf = 0; nf < 4; nf++) {
                int n = ncol + nf * 8 + gid;
                bf[nf][0] = f2tf(Bs[cur][kk + tig    ][n]);
                bf[nf][1] = f2tf(Bs[cur][kk + tig + 4][n]);
            }
#pragma unroll
            for (int mf = 0; mf < 4; mf++)
#pragma unroll
                for (int nf = 0; nf < 4; nf++) {
                    asm volatile(
                        "mma.sync.aligned.m16n8k8.row.col.f32.tf32.tf32.f32 "
                        "{%0,%1,%2,%3}, {%4,%5,%6,%7}, {%8,%9}, {%0,%1,%2,%3};\n"
                        : "+f"(acc[mf][nf][0]), "+f"(acc[mf][nf][1]),
                          "+f"(acc[mf][nf][2]), "+f"(acc[mf][nf][3])
                        : "r"(a[mf][0]), "r"(a[mf][1]),
                          "r"(a[mf][2]), "r"(a[mf][3]),
                          "r"(bf[nf][0]), "r"(bf[nf][1]));
                }
        }
        __syncthreads();
    }

    // ---- epilogue: bias (+ReLU), float2 stores ----
    const int mrow = wm * 64;
    const int ncol = wn * 32;
#pragma unroll
    for (int nf = 0; nf < 4; nf++) {
        int gcol = bx * BN + ncol + nf * 8 + tig * 2;
        float b0 = bias[gcol], b1 = bias[gcol + 1];
#pragma unroll
        for (int mf = 0; mf < 4; mf++) {
            int grow = by * BM + mrow + mf * 16 + gid;
            float2 v0, v1;
            v0.x = acc[mf][nf][0] + b0;  v0.y = acc[mf][nf][1] + b1;
            v1.x = acc[mf][nf][2] + b0;  v1.y = acc[mf][nf][3] + b1;
            if (RELU) {
                v0.x = fmaxf(v0.x, 0.f); v0.y = fmaxf(v0.y, 0.f);
                v1.x = fmaxf(v1.x, 0.f); v1.y = fmaxf(v1.y, 0.f);
            }
            *(float2*)(C + (size_t)grow * N + gcol)       = v0;
            *(float2*)(C + (size_t)(grow + 8) * N + gcol) = v1;
        }
    }
}

// ---------------------------------------------------------------------------
// q = cur_src + pos[:, 3]   (level-3 slice of pos)
// ---------------------------------------------------------------------------
__global__ void q_kernel(const float* __restrict__ cur,
                         const float* __restrict__ pos,
                         float* __restrict__ q)
{
    size_t t = (size_t)blockIdx.x * blockDim.x + threadIdx.x;   // float4 index
    const size_t per_batch = (size_t)LQ * D_MODEL / 4;
    size_t n = t / per_batch;
    size_t r = t - n * per_batch;
    float4 a = ((const float4*)cur)[t];
    float4 b = ((const float4*)pos)[(n * N_LEVELS + (N_LEVELS - 1)) * per_batch + r];
    a.x += b.x; a.y += b.y; a.z += b.z; a.w += b.w;
    ((float4*)q)[t] = a;
}

// ---------------------------------------------------------------------------
// In-place softmax over groups of 16 (per n,q,head)
// ---------------------------------------------------------------------------
__global__ void softmax16_kernel(float* __restrict__ attn)
{
    int t = blockIdx.x * blockDim.x + threadIdx.x;
    float* p = attn + (size_t)(t >> 3) * 128 + (t & 7) * 16;
    float4 v[4];
#pragma unroll
    for (int i = 0; i < 4; i++) v[i] = ((float4*)p)[i];
    float* f = (float*)v;
    float mx = f[0];
#pragma unroll
    for (int i = 1; i < 16; i++) mx = fmaxf(mx, f[i]);
    float s = 0.f;
#pragma unroll
    for (int i = 0; i < 16; i++) { f[i] = expf(f[i] - mx); s += f[i]; }
    float inv = 1.f / s;
#pragma unroll
    for (int i = 0; i < 16; i++) f[i] *= inv;
#pragma unroll
    for (int i = 0; i < 4; i++) ((float4*)p)[i] = v[i];
}

// ---------------------------------------------------------------------------
// Deformable attention sampling. One warp per (n, q, head); lane = channel.
// ---------------------------------------------------------------------------
__global__ void __launch_bounds__(256)
sample_kernel(const float* __restrict__ ref, float* __restrict__ out)
{
    int wg   = (blockIdx.x * blockDim.x + threadIdx.x) >> 5;
    int lane = threadIdx.x & 31;
    int h = wg & 7;
    int q = (wg >> 3) & (LQ - 1);
    int n = wg >> 17;

    const size_t nq = (size_t)n * LQ + q;
    const float* offp  = g_off  + nq * 256 + h * 32;
    const float* attnp = g_attn + nq * 128 + h * 16;
    const float* refp  = ref    + nq * (N_LEVELS * 2);

    float acc = 0.f;

#pragma unroll
    for (int l = 0; l < N_LEVELS; l++) {
        float rx = refp[l * 2 + 0] * (float)HW - 0.5f;
        float ry = refp[l * 2 + 1] * (float)HW - 0.5f;
        const float* vbase = g_value
            + ((size_t)(n * LIN + l * LQ)) * D_MODEL + h * 32 + lane;

#pragma unroll
        for (int p = 0; p < N_POINTS; p++) {
            float x  = rx + offp[l * 8 + p * 2 + 0];
            float y  = ry + offp[l * 8 + p * 2 + 1];
            float aw = attnp[l * 4 + p];

            float x0f = floorf(x), y0f = floorf(y);
            float wx = x - x0f, wy = y - y0f;
            int x0 = (int)x0f, y0 = (int)y0f;
            int x1 = x0 + 1,   y1 = y0 + 1;

            float mx0 = (x0 >= 0 && x0 < HW) ? 1.f : 0.f;
            float mx1 = (x1 >= 0 && x1 < HW) ? 1.f : 0.f;
            float my0 = (y0 >= 0 && y0 < HW) ? 1.f : 0.f;
            float my1 = (y1 >= 0 && y1 < HW) ? 1.f : 0.f;

            int cx0 = min(max(x0, 0), HW - 1);
            int cx1 = min(max(x1, 0), HW - 1);
            int cy0 = min(max(y0, 0), HW - 1);
            int cy1 = min(max(y1, 0), HW - 1);

            float w00 = (1.f - wx) * (1.f - wy) * mx0 * my0;
            float w10 = wx * (1.f - wy) * mx1 * my0;
            float w01 = (1.f - wx) * wy * mx0 * my1;
            float w11 = wx * wy * mx1 * my1;

            float v00 = vbase[(size_t)(cy0 * HW + cx0) * D_MODEL];
            float v10 = vbase[(size_t)(cy0 * HW + cx1) * D_MODEL];
            float v01 = vbase[(size_t)(cy1 * HW + cx0) * D_MODEL];
            float v11 = vbase[(size_t)(cy1 * HW + cx1) * D_MODEL];

            float s = w00 * v00 + w10 * v10 + w01 * v01 + w11 * v11;
            acc = fmaf(aw, s, acc);
        }
    }

    out[nq * D_MODEL + h * 32 + lane] = acc;
}

// ---------------------------------------------------------------------------
// Fused residual-add + LayerNorm over 256-wide rows. One warp per row.
// ---------------------------------------------------------------------------
__global__ void __launch_bounds__(256)
add_ln_kernel(const float* __restrict__ a, const float* __restrict__ b,
              const float* __restrict__ gamma, const float* __restrict__ beta,
              float* __restrict__ out)
{
    int row  = (blockIdx.x * blockDim.x + threadIdx.x) >> 5;
    int lane = threadIdx.x & 31;

    const float4* a4 = (const float4*)(a + (size_t)row * D_MODEL);
    const float4* b4 = (const float4*)(b + (size_t)row * D_MODEL);

    float x[8];
    float4 va0 = a4[lane * 2 + 0], vb0 = b4[lane * 2 + 0];
    float4 va1 = a4[lane * 2 + 1], vb1 = b4[lane * 2 + 1];
    x[0] = va0.x + vb0.x; x[1] = va0.y + vb0.y;
    x[2] = va0.z + vb0.z; x[3] = va0.w + vb0.w;
    x[4] = va1.x + vb1.x; x[5] = va1.y + vb1.y;
    x[6] = va1.z + vb1.z; x[7] = va1.w + vb1.w;

    float s = 0.f, ss = 0.f;
#pragma unroll
    for (int i = 0; i < 8; i++) { s += x[i]; ss = fmaf(x[i], x[i], ss); }
#pragma unroll
    for (int d = 16; d > 0; d >>= 1) {
        s  += __shfl_xor_sync(0xffffffffu, s,  d);
        ss += __shfl_xor_sync(0xffffffffu, ss, d);
    }
    float mean = s * (1.f / D_MODEL);
    float var  = ss * (1.f / D_MODEL) - mean * mean;
    float inv  = rsqrtf(var + 1e-5f);

    float o[8];
#pragma unroll
    for (int i = 0; i < 8; i++) {
        int c = lane * 8 + i;
        o[i] = (x[i] - mean) * inv * gamma[c] + beta[c];
    }
    float4* o4 = (float4*)(out + (size_t)row * D_MODEL);
    o4[lane * 2 + 0] = make_float4(o[0], o[1], o[2], o[3]);
    o4[lane * 2 + 1] = make_float4(o[4], o[5], o[6], o[7]);
}

// ---------------------------------------------------------------------------
// Launch
// ---------------------------------------------------------------------------
extern "C" void kernel_launch(void* const* d_in, const int* in_sizes, int n_in,
                              void* d_out, int out_size)
{
    const float* cur_src = (const float*)d_in[0];
    const float* src_all = (const float*)d_in[1];
    const float* pos     = (const float*)d_in[2];
    const float* refpts  = (const float*)d_in[3];
    const float* W_off  = (const float*)d_in[6];
    const float* b_off  = (const float*)d_in[7];
    const float* W_attn = (const float*)d_in[8];
    const float* b_attn = (const float*)d_in[9];
    const float* W_val  = (const float*)d_in[10];
    const float* b_val  = (const float*)d_in[11];
    const float* W_out  = (const float*)d_in[12];
    const float* b_out  = (const float*)d_in[13];
    const float* gamma1 = (const float*)d_in[14];
    const float* beta1  = (const float*)d_in[15];
    const float* W1     = (const float*)d_in[16];
    const float* b1     = (const float*)d_in[17];
    const float* W2     = (const float*)d_in[18];
    const float* b2     = (const float*)d_in[19];
    const float* gamma2 = (const float*)d_in[20];
    const float* beta2  = (const float*)d_in[21];
    float* out = (float*)d_out;

    float *q_buf, *value_buf, *off_buf, *attn_buf, *attnout_buf,
          *src2_buf, *src_buf, *ffn_buf;
    cudaGetSymbolAddress((void**)&q_buf,       g_q);
    cudaGetSymbolAddress((void**)&value_buf,   g_value);
    cudaGetSymbolAddress((void**)&off_buf,     g_off);
    cudaGetSymbolAddress((void**)&attn_buf,    g_attn);
    cudaGetSymbolAddress((void**)&attnout_buf, g_attnout);
    cudaGetSymbolAddress((void**)&src2_buf,    g_src2);
    cudaGetSymbolAddress((void**)&src_buf,     g_src);
    cudaGetSymbolAddress((void**)&ffn_buf,     g_ffn);

    // 1) q = cur_src + pos[:,-1]
    {
        int nvec = M_Q * D_MODEL / 4;
        q_kernel<<<nvec / 256, 256>>>(cur_src, pos, q_buf);
    }

    // 2) value = (src_all + pos_flat) @ W_val + b_val   (add fused into A load)
    mma_gemm<false, true><<<dim3(D_MODEL / BN, M_V / BM), 256>>>(
        src_all, pos, W_val, b_val, value_buf, M_V, D_MODEL, D_MODEL);

    // 3) off = q @ W_off + b_off
    mma_gemm<false, false><<<dim3(D_MODEL / BN, M_Q / BM), 256>>>(
        q_buf, nullptr, W_off, b_off, off_buf, M_Q, D_MODEL, D_MODEL);

    // 4) attn logits = q @ W_attn + b_attn
    mma_gemm<false, false><<<dim3(128 / BN, M_Q / BM), 256>>>(
        q_buf, nullptr, W_attn, b_attn, attn_buf, M_Q, 128, D_MODEL);

    // 5) softmax over 16-groups
    softmax16_kernel<<<(M_Q * N_HEADS) / 256, 256>>>(attn_buf);

    // 6) deformable sampling
    sample_kernel<<<(M_Q * N_HEADS * 32) / 256, 256>>>(refpts, attnout_buf);

    // 7) src2 = attnout @ W_out + b_out
    mma_gemm<false, false><<<dim3(D_MODEL / BN, M_Q / BM), 256>>>(
        attnout_buf, nullptr, W_out, b_out, src2_buf, M_Q, D_MODEL, D_MODEL);

    // 8) src = LN(cur_src + src2)
    add_ln_kernel<<<(M_Q * 32) / 256, 256>>>(
        cur_src, src2_buf, gamma1, beta1, src_buf);

    // 9) ffn hidden = relu(src @ W1 + b1)
    mma_gemm<true, false><<<dim3(D_FFN / BN, M_Q / BM), 256>>>(
        src_buf, nullptr, W1, b1, ffn_buf, M_Q, D_FFN, D_MODEL);

    // 10) ffn out = hidden @ W2 + b2
    mma_gemm<false, false><<<dim3(D_MODEL / BN, M_Q / BM), 256>>>(
        ffn_buf, nullptr, W2, b2, src2_buf, M_Q, D_MODEL, D_FFN);

    // 11) out = LN(src + ffn_out)
    add_ln_kernel<<<(M_Q * 32) / 256, 256>>>(
        src_buf, src2_buf, gamma2, beta2, out);
}